// round 4
// baseline (speedup 1.0000x reference)
#include <cuda_runtime.h>
#include <math.h>

#define BB 4
#define SS 4096
#define DD 1024
#define KK 8
#define RC 256
#define MIDD 256

// ---------------- scratch (device globals; no allocs allowed) ----------------
__device__ float g_RBs[16 * MIDD];          // row_basis.sum(axis=1)   [16,256]
__device__ float g_CBs[16 * MIDD];          // col_basis.sum(axis=2)   [16,256]
__device__ float g_Ms[16 * 16];             // (RBs·CBsT) * log2e/16   [16,16]
__device__ float g_CB2[16 * DD];            // col_basis.sum(axis=1)   [16,1024]
__device__ float g_U[BB * SS * 16];
__device__ float g_V[BB * SS * 16];
__device__ float g_Lr[BB * SS];             // 1/rowsum of exp
__device__ float g_P[(size_t)BB * SS * SS]; // unnormalized probs (lower tri)
__device__ float g_H[(size_t)BB * SS * DD]; // gelu(context + alpha*transform)
__device__ float g_Wt[DD * DD];             // out_w transposed [k][j]

// ---------------- helpers ----------------
__device__ __forceinline__ unsigned long long pk2(float a, float b) {
    unsigned long long r;
    asm("mov.b64 %0, {%1, %2};" : "=l"(r) : "f"(a), "f"(b));
    return r;
}
__device__ __forceinline__ void ffma2(unsigned long long& d, unsigned long long a, unsigned long long b) {
    asm("fma.rn.f32x2 %0, %1, %2, %0;" : "+l"(d) : "l"(a), "l"(b));
}
__device__ __forceinline__ float2 upk(unsigned long long v) {
    float2 r;
    asm("mov.b64 {%0, %1}, %2;" : "=f"(r.x), "=f"(r.y) : "l"(v));
    return r;
}
// 2^x for x in ~[-60, 8], rel err ~1e-5, pure FMA pipe (avoids MUFU ceiling)
__device__ __forceinline__ float fexp2(float x) {
    x = fmaxf(x, -60.0f);
    float fl = floorf(x);
    float f = x - fl;
    float p = 1.5403530393e-4f;
    p = fmaf(p, f, 1.3333558146e-3f);
    p = fmaf(p, f, 9.6181291076e-3f);
    p = fmaf(p, f, 5.5504108664e-2f);
    p = fmaf(p, f, 2.4022650696e-1f);
    p = fmaf(p, f, 6.9314718056e-1f);
    p = fmaf(p, f, 1.0f);
    int e = (int)fl;
    return p * __int_as_float((e + 127) << 23);
}
__device__ __forceinline__ float gelu_exact(float v) {
    return 0.5f * v * (1.0f + erff(v * 0.70710678118654752f));
}

// ---------------- stage 1: basis reductions ----------------
__global__ void k_rbs(const float* __restrict__ rb) {
    int r = blockIdx.x, m = threadIdx.x; // 16 blocks x 256
    const float* src = rb + (size_t)r * DD * MIDD + m;
    float s = 0.f;
    for (int d = 0; d < DD; ++d) s += src[(size_t)d * MIDD];
    g_RBs[r * MIDD + m] = s;
}
__global__ void k_cbs(const float* __restrict__ cb) {
    int gw = (blockIdx.x * blockDim.x + threadIdx.x) >> 5; // warp per (c,m)
    int lane = threadIdx.x & 31;
    int c = gw >> 8, m = gw & 255;
    const float* src = cb + (size_t)c * MIDD * DD + (size_t)m * DD;
    float s = 0.f;
    for (int d = lane; d < DD; d += 32) s += src[d];
#pragma unroll
    for (int o = 16; o; o >>= 1) s += __shfl_xor_sync(0xffffffffu, s, o);
    if (lane == 0) g_CBs[c * MIDD + m] = s;
}
__global__ void k_cb2(const float* __restrict__ cb) {
    int idx = blockIdx.x * blockDim.x + threadIdx.x; // 64 x 256 = 16384
    int c = idx >> 10, d = idx & 1023;
    const float* src = cb + (size_t)c * MIDD * DD + d;
    float s = 0.f;
    for (int m = 0; m < MIDD; ++m) s += src[(size_t)m * DD];
    g_CB2[c * DD + d] = s;
}
__global__ void k_M() {
    int r = threadIdx.x >> 4, c = threadIdx.x & 15; // 1 block x 256
    float s = 0.f;
    for (int m = 0; m < MIDD; ++m) s = fmaf(g_RBs[r * MIDD + m], g_CBs[c * MIDD + m], s);
    g_Ms[r * 16 + c] = s * (1.4426950408889634f / 16.0f); // fold 1/sqrt(256) and log2e
}

// ---------------- stage 2: routing -> U, V (warp per token) ----------------
__global__ void k_route(const int* __restrict__ nidx, const float* __restrict__ nw,
                        const float* __restrict__ nrec) {
    int n = (blockIdx.x * blockDim.x + threadIdx.x) >> 5;
    int lane = threadIdx.x & 31;
    float acc[8];
#pragma unroll
    for (int j = 0; j < 8; ++j) acc[j] = 0.f;
#pragma unroll
    for (int k = 0; k < KK; ++k) {
        int id = __ldg(&nidx[n * KK + k]);
        float w = __ldg(&nw[n * KK + k]);
        const float* base = nrec + (size_t)id * RC;
        float e[8];
        float s = 0.f;
#pragma unroll
        for (int j = 0; j < 8; ++j) { // values ~N(0,0.02): max-free softmax safe
            float v = __expf(base[lane + 32 * j]);
            e[j] = v; s += v;
        }
#pragma unroll
        for (int o = 16; o; o >>= 1) s += __shfl_xor_sync(0xffffffffu, s, o);
        float ws = w / s;
#pragma unroll
        for (int j = 0; j < 8; ++j) acc[j] = fmaf(e[j], ws, acc[j]);
    }
    // second softmax (args in [0, ~1]: max-free safe)
    float e2[8];
    float s2 = 0.f;
#pragma unroll
    for (int j = 0; j < 8; ++j) { float v = __expf(acc[j]); e2[j] = v; s2 += v; }
#pragma unroll
    for (int o = 16; o; o >>= 1) s2 += __shfl_xor_sync(0xffffffffu, s2, o);
    float inv2 = 1.0f / s2;
    // colsum: element p = lane + 32j has col = lane&15
    float tsum = 0.f;
#pragma unroll
    for (int j = 0; j < 8; ++j) tsum += e2[j];
    tsum *= inv2;
    float cs = tsum + __shfl_xor_sync(0xffffffffu, tsum, 16);
    // rowsum: element p has row = 2j + (lane>>4)
    float rs[8];
#pragma unroll
    for (int j = 0; j < 8; ++j) {
        float v = e2[j] * inv2;
        v += __shfl_xor_sync(0xffffffffu, v, 1);
        v += __shfl_xor_sync(0xffffffffu, v, 2);
        v += __shfl_xor_sync(0xffffffffu, v, 4);
        v += __shfl_xor_sync(0xffffffffu, v, 8);
        rs[j] = v;
    }
    // u[i] = sum_r rowsum[r] * Ms[r][i]
    float u = 0.f;
#pragma unroll
    for (int r = 0; r < 16; ++r) {
        float rw = __shfl_sync(0xffffffffu, rs[r >> 1], (r & 1) << 4);
        if (lane < 16) u = fmaf(rw, g_Ms[r * 16 + lane], u);
    }
    if (lane < 16) {
        g_U[(size_t)n * 16 + lane] = u;
        g_V[(size_t)n * 16 + lane] = cs;
    }
}

// ---------------- stage 3: P = exp2(U·V) (unnormalized), Lr = 1/rowsum ----------------
__global__ void k_smax() {
    int b = blockIdx.y;
    int qt = (gridDim.x - 1) - blockIdx.x; // big tiles first
    int tid = threadIdx.x;
    int row = tid >> 2, sub = tid & 3;
    int wid = tid >> 5, lane = tid & 31;
    int qg = qt * 64 + row;
    __shared__ float Vs[64 * 20];
    __shared__ float Ps[64 * 66];
    __shared__ float lsum[64];
    if (tid < 64) lsum[tid] = 0.f;
    float ur[16];
    const float* up = g_U + ((size_t)b * SS + qg) * 16;
#pragma unroll
    for (int i = 0; i < 16; ++i) ur[i] = up[i];

    for (int kt = 0; kt <= qt; ++kt) {
        __syncthreads();
        { // load V tile
            int vr = tid >> 2, c4 = (tid & 3) * 4;
            float4 v = *(const float4*)(g_V + ((size_t)b * SS + (size_t)kt * 64 + vr) * 16 + c4);
            float* d = Vs + vr * 20 + c4;
            d[0] = v.x; d[1] = v.y; d[2] = v.z; d[3] = v.w;
        }
        __syncthreads();
        float psum = 0.f;
        bool diag = (kt == qt);
#pragma unroll
        for (int j = 0; j < 16; ++j) {
            int key = sub + 4 * j;
            const float* vv = Vs + key * 20;
            float s = 0.f;
#pragma unroll
            for (int i = 0; i < 16; ++i) s = fmaf(ur[i], vv[i], s);
            float p = (diag && key > row) ? 0.f : fexp2(s);
            Ps[row * 66 + key] = p;
            psum += p;
        }
        psum += __shfl_xor_sync(0xffffffffu, psum, 1);
        psum += __shfl_xor_sync(0xffffffffu, psum, 2);
        if (sub == 0) lsum[row] += psum;
        __syncthreads();
        // coalesced write of the 64x64 tile
        float* gp = g_P + ((size_t)b * SS + (size_t)qt * 64) * SS + (size_t)kt * 64;
#pragma unroll
        for (int r = 0; r < 8; ++r) {
            int rr = wid * 8 + r;
            float2 v2 = *(float2*)(Ps + rr * 66 + 2 * lane);
            *(float2*)(gp + (size_t)rr * SS + 2 * lane) = v2;
        }
    }
    __syncthreads();
    if (tid < 64) g_Lr[(size_t)b * SS + (size_t)qt * 64 + tid] = 1.0f / lsum[tid];
}

// ---------------- stage 4: context GEMM (P@x) + transform + gelu -> H ----------------
#define CTX_SMEM ((64 * 260 + 64 * 66 + 16 * 256 + 64 * 16) * 4)
__global__ void __launch_bounds__(256, 2) k_ctx(const float* __restrict__ x,
                                                const float* __restrict__ alphap) {
    int dc = blockIdx.x;                       // 4 chunks of 256 over D
    int qt = (gridDim.y - 1) - blockIdx.y;     // big first
    int b = blockIdx.z;
    int tid = threadIdx.x;
    int tq = tid >> 5, td = tid & 31;          // warp id, lane
    extern __shared__ float sm[];
    float* Xs = sm;                 // [64][260]
    float* Psm = Xs + 64 * 260;     // [64][66]
    float* C2 = Psm + 64 * 66;      // [16][256]
    float* Vqs = C2 + 16 * 256;     // [64][16]
    int dc0 = dc * 256;
    { // one-time loads
        int r = tid >> 4, cbase = (tid & 15) * 16;
        const float* src = g_CB2 + (size_t)r * DD + dc0 + cbase;
        float* dst = C2 + r * 256 + cbase;
#pragma unroll
        for (int k = 0; k < 4; ++k) *(float4*)(dst + 4 * k) = *(const float4*)(src + 4 * k);
        int vr = tid >> 2, c4 = (tid & 3) * 4;
        *(float4*)(Vqs + vr * 16 + c4) =
            *(const float4*)(g_V + ((size_t)b * SS + (size_t)qt * 64 + vr) * 16 + c4);
    }
    unsigned long long acc[8][4];
#pragma unroll
    for (int i = 0; i < 8; ++i)
#pragma unroll
        for (int j = 0; j < 4; ++j) acc[i][j] = 0ull;

    const float* xb = x + (size_t)b * SS * DD;
    const float* pb = g_P + ((size_t)b * SS + (size_t)qt * 64) * SS;

    for (int kt = 0; kt <= qt; ++kt) {
        __syncthreads();
        { // X tile [64 t][256 d]
            int r0 = tid >> 4, c16 = tid & 15;
#pragma unroll
            for (int rb = 0; rb < 4; ++rb) {
                int t = rb * 16 + r0;
                const float* src = xb + ((size_t)kt * 64 + t) * DD + dc0;
                float* dst = Xs + t * 260;
#pragma unroll
                for (int k = 0; k < 4; ++k) {
                    int c = (c16 + 16 * k) * 4;
                    *(float4*)(dst + c) = *(const float4*)(src + c);
                }
            }
            // P tile [64 q][64 t]
#pragma unroll
            for (int r = 0; r < 8; ++r) {
                int rr = tq * 8 + r;
                float2 v = *(const float2*)(pb + (size_t)rr * SS + (size_t)kt * 64 + 2 * td);
                *(float2*)(Psm + rr * 66 + 2 * td) = v;
            }
        }
        __syncthreads();
#pragma unroll 8
        for (int t = 0; t < 64; ++t) {
            unsigned long long x0 = *(const unsigned long long*)(Xs + t * 260 + 2 * td);
            unsigned long long x1 = *(const unsigned long long*)(Xs + t * 260 + 2 * td + 64);
            unsigned long long x2 = *(const unsigned long long*)(Xs + t * 260 + 2 * td + 128);
            unsigned long long x3 = *(const unsigned long long*)(Xs + t * 260 + 2 * td + 192);
#pragma unroll
            for (int i = 0; i < 8; ++i) {
                float p = Psm[(tq * 8 + i) * 66 + t];
                unsigned long long pp = pk2(p, p);
                ffma2(acc[i][0], pp, x0);
                ffma2(acc[i][1], pp, x1);
                ffma2(acc[i][2], pp, x2);
                ffma2(acc[i][3], pp, x3);
            }
        }
    }
    // epilogue: normalize, add alpha*transform, exact gelu, store H
    float alpha = *alphap;
#pragma unroll
    for (int i = 0; i < 8; ++i) {
        int qg = qt * 64 + tq * 8 + i;
        float lr = g_Lr[(size_t)b * SS + qg];
        float* hq = g_H + ((size_t)b * SS + qg) * DD + dc0;
        const float* vq = Vqs + (tq * 8 + i) * 16;
#pragma unroll
        for (int j = 0; j < 4; ++j) {
            int dloc = 2 * td + 64 * j;
            float2 o = upk(acc[i][j]);
            float trx = 0.f, trY = 0.f;
#pragma unroll
            for (int c = 0; c < 16; ++c) {
                float vv = vq[c];
                trx = fmaf(vv, C2[c * 256 + dloc], trx);
                trY = fmaf(vv, C2[c * 256 + dloc + 1], trY);
            }
            float vx = fmaf(o.x, lr, alpha * trx);
            float vy = fmaf(o.y, lr, alpha * trY);
            vx = gelu_exact(vx);
            vy = gelu_exact(vy);
            *(float2*)(hq + dloc) = make_float2(vx, vy);
        }
    }
}

// ---------------- stage 5: transpose out_w ----------------
__global__ void k_tr(const float* __restrict__ w) {
    __shared__ float t[32][33];
    int bx = blockIdx.x * 32, by = blockIdx.y * 32;
    int x = bx + threadIdx.x;
    int y = by + threadIdx.y;
#pragma unroll
    for (int i = 0; i < 32; i += 8) t[threadIdx.y + i][threadIdx.x] = w[(size_t)(y + i) * DD + x];
    __syncthreads();
    int xo = by + threadIdx.x;
    int yo = bx + threadIdx.y;
#pragma unroll
    for (int i = 0; i < 32; i += 8) g_Wt[(size_t)(yo + i) * DD + xo] = t[threadIdx.x][threadIdx.y + i];
}

// ---------------- stage 6: out = H @ Wt + b ----------------
#define OUT_SMEM ((64 * 260 + 64 * 66) * 4)
__global__ void __launch_bounds__(256, 2) k_out(const float* __restrict__ ob,
                                                float* __restrict__ out) {
    int jc = blockIdx.x;  // 4 chunks of 256 over D
    int nt = blockIdx.y;  // 256 row tiles of 64
    int tid = threadIdx.x;
    int tq = tid >> 5, td = tid & 31;
    extern __shared__ float sm[];
    float* Ws = sm;             // [64 k][260 j]
    float* Hs = Ws + 64 * 260;  // [64 n][66 k]
    int jc0 = jc * 256;
    unsigned long long acc[8][4];
#pragma unroll
    for (int i = 0; i < 8; ++i)
#pragma unroll
        for (int j = 0; j < 4; ++j) acc[i][j] = 0ull;

    for (int kt = 0; kt < 16; ++kt) {
        __syncthreads();
        {
            int r0 = tid >> 4, c16 = tid & 15;
#pragma unroll
            for (int rb = 0; rb < 4; ++rb) {
                int t = rb * 16 + r0;
                const float* src = g_Wt + ((size_t)kt * 64 + t) * DD + jc0;
                float* dst = Ws + t * 260;
#pragma unroll
                for (int k = 0; k < 4; ++k) {
                    int c = (c16 + 16 * k) * 4;
                    *(float4*)(dst + c) = *(const float4*)(src + c);
                }
            }
#pragma unroll
            for (int r = 0; r < 8; ++r) {
                int rr = tq * 8 + r;
                float2 v = *(const float2*)(g_H + ((size_t)nt * 64 + rr) * DD + (size_t)kt * 64 + 2 * td);
                *(float2*)(Hs + rr * 66 + 2 * td) = v;
            }
        }
        __syncthreads();
#pragma unroll 8
        for (int t = 0; t < 64; ++t) {
            unsigned long long w0 = *(const unsigned long long*)(Ws + t * 260 + 2 * td);
            unsigned long long w1 = *(const unsigned long long*)(Ws + t * 260 + 2 * td + 64);
            unsigned long long w2 = *(const unsigned long long*)(Ws + t * 260 + 2 * td + 128);
            unsigned long long w3 = *(const unsigned long long*)(Ws + t * 260 + 2 * td + 192);
#pragma unroll
            for (int i = 0; i < 8; ++i) {
                float h = Hs[(tq * 8 + i) * 66 + t];
                unsigned long long hh = pk2(h, h);
                ffma2(acc[i][0], hh, w0);
                ffma2(acc[i][1], hh, w1);
                ffma2(acc[i][2], hh, w2);
                ffma2(acc[i][3], hh, w3);
            }
        }
    }
#pragma unroll
    for (int i = 0; i < 8; ++i) {
        int n = nt * 64 + tq * 8 + i;
        float* op = out + (size_t)n * DD + jc0;
#pragma unroll
        for (int j = 0; j < 4; ++j) {
            int dloc = 2 * td + 64 * j;
            float2 o = upk(acc[i][j]);
            o.x += ob[jc0 + dloc];
            o.y += ob[jc0 + dloc + 1];
            *(float2*)(op + dloc) = o;
        }
    }
}

// ---------------- launcher ----------------
extern "C" void kernel_launch(void* const* d_in, const int* in_sizes, int n_in,
                              void* d_out, int out_size) {
    const float* x    = (const float*)d_in[0];
    const int*   nidx = (const int*)d_in[1];
    const float* nw   = (const float*)d_in[2];
    const float* nrec = (const float*)d_in[3];
    const float* rb   = (const float*)d_in[4];
    const float* cb   = (const float*)d_in[5];
    const float* ow   = (const float*)d_in[6];
    const float* ob   = (const float*)d_in[7];
    const float* alp  = (const float*)d_in[8];
    float* out = (float*)d_out;

    cudaFuncSetAttribute(k_ctx, cudaFuncAttributeMaxDynamicSharedMemorySize, CTX_SMEM);
    cudaFuncSetAttribute(k_out, cudaFuncAttributeMaxDynamicSharedMemorySize, OUT_SMEM);

    k_rbs<<<16, 256>>>(rb);
    k_cbs<<<512, 256>>>(cb);
    k_cb2<<<64, 256>>>(cb);
    k_M<<<1, 256>>>();
    k_route<<<(BB * SS * 32) / 256, 256>>>(nidx, nw, nrec);
    k_smax<<<dim3(64, BB), 256>>>();
    k_ctx<<<dim3(4, 64, BB), 256, CTX_SMEM>>>(x, alp);
    k_tr<<<dim3(32, 32), dim3(32, 8)>>>(ow);
    k_out<<<dim3(4, 256), 256, OUT_SMEM>>>(ob, out);
}

// round 6
// speedup vs baseline: 2.3194x; 2.3194x over previous
#include <cuda_runtime.h>
#include <cuda.h>
#include <math.h>
#include <stdint.h>

#define BB 4
#define SS 4096
#define DD 1024
#define KK 8
#define RC 256
#define MIDD 256

// ---------------- scratch (device globals; no allocs allowed) ----------------
__device__ float g_RBs[16 * MIDD];
__device__ float g_CBs[16 * MIDD];
__device__ float g_Ms[16 * 16];
__device__ float g_CB2[16 * DD];
__device__ float g_U[BB * SS * 16];
__device__ float g_V[BB * SS * 16];
__device__ float g_Lr[BB * SS];
__device__ float g_P[(size_t)BB * SS * SS];  // tf32-rounded, lower-tri (+zeroed pad tile)
__device__ float g_Xt[(size_t)BB * DD * SS]; // x transposed [b][d][t], tf32-rounded
__device__ float g_H[(size_t)BB * SS * DD];  // tf32-rounded gelu output
__device__ float g_Wr[DD * DD];              // out_w tf32-rounded [j][k]

// ---------------- helpers ----------------
__device__ __forceinline__ float tf32r(float x) {
    float r; asm("cvt.rna.tf32.f32 %0, %1;" : "=f"(r) : "f"(x)); return r;
}
__device__ __forceinline__ float fexp2(float x) {
    x = fmaxf(x, -60.0f);
    float fl = floorf(x);
    float f = x - fl;
    float p = 1.5403530393e-4f;
    p = fmaf(p, f, 1.3333558146e-3f);
    p = fmaf(p, f, 9.6181291076e-3f);
    p = fmaf(p, f, 5.5504108664e-2f);
    p = fmaf(p, f, 2.4022650696e-1f);
    p = fmaf(p, f, 6.9314718056e-1f);
    p = fmaf(p, f, 1.0f);
    int e = (int)fl;
    return p * __int_as_float((e + 127) << 23);
}
__device__ __forceinline__ float gelu_exact(float v) {
    return 0.5f * v * (1.0f + erff(v * 0.70710678118654752f));
}
__device__ __forceinline__ uint32_t s2u(const void* p) {
    uint32_t a;
    asm("{ .reg .u64 t; cvta.to.shared.u64 t, %1; cvt.u32.u64 %0, t; }" : "=r"(a) : "l"(p));
    return a;
}
__device__ __forceinline__ void cpa16(uint32_t dst, const void* src) {
    asm volatile("cp.async.cg.shared.global [%0], [%1], 16;" :: "r"(dst), "l"(src));
}
#define CPA_COMMIT() asm volatile("cp.async.commit_group;" ::: "memory")

__device__ __forceinline__ void mma_tf32(float* c, const uint32_t* a, const uint32_t* b) {
    asm volatile(
        "mma.sync.aligned.m16n8k8.row.col.f32.tf32.tf32.f32 "
        "{%0,%1,%2,%3}, {%4,%5,%6,%7}, {%8,%9}, {%0,%1,%2,%3};"
        : "+f"(c[0]), "+f"(c[1]), "+f"(c[2]), "+f"(c[3])
        : "r"(a[0]), "r"(a[1]), "r"(a[2]), "r"(a[3]), "r"(b[0]), "r"(b[1]));
}

// SMEM tiling for the mma GEMMs
#define APAD 36
#define ABUF (128 * APAD)       // 4608 floats per A (or B) tile
#define BUFSZ (2 * ABUF)        // A+B per buffer = 9216 floats
#define GSMEM_MMA (2 * BUFSZ * 4)  // 73728 bytes

// ---------------- stage 1: basis reductions ----------------
__global__ void k_rbs(const float* __restrict__ rb) {
    int r = blockIdx.x, m = threadIdx.x;
    const float* src = rb + (size_t)r * DD * MIDD + m;
    float s = 0.f;
    for (int d = 0; d < DD; ++d) s += src[(size_t)d * MIDD];
    g_RBs[r * MIDD + m] = s;
}
__global__ void k_cbs(const float* __restrict__ cb) {
    int gw = (blockIdx.x * blockDim.x + threadIdx.x) >> 5;
    int lane = threadIdx.x & 31;
    int c = gw >> 8, m = gw & 255;
    const float* src = cb + (size_t)c * MIDD * DD + (size_t)m * DD;
    float s = 0.f;
    for (int d = lane; d < DD; d += 32) s += src[d];
#pragma unroll
    for (int o = 16; o; o >>= 1) s += __shfl_xor_sync(0xffffffffu, s, o);
    if (lane == 0) g_CBs[c * MIDD + m] = s;
}
__global__ void k_cb2(const float* __restrict__ cb) {
    int idx = blockIdx.x * blockDim.x + threadIdx.x;
    int c = idx >> 10, d = idx & 1023;
    const float* src = cb + (size_t)c * MIDD * DD + d;
    float s = 0.f;
    for (int m = 0; m < MIDD; ++m) s += src[(size_t)m * DD];
    g_CB2[c * DD + d] = s;
}
__global__ void k_M() {
    int r = threadIdx.x >> 4, c = threadIdx.x & 15;
    float s = 0.f;
    for (int m = 0; m < MIDD; ++m) s = fmaf(g_RBs[r * MIDD + m], g_CBs[c * MIDD + m], s);
    g_Ms[r * 16 + c] = s * (1.4426950408889634f / 16.0f);
}

// ---------------- stage 2: routing -> U, V ----------------
__global__ void k_route(const int* __restrict__ nidx, const float* __restrict__ nw,
                        const float* __restrict__ nrec) {
    int n = (blockIdx.x * blockDim.x + threadIdx.x) >> 5;
    int lane = threadIdx.x & 31;
    float acc[8];
#pragma unroll
    for (int j = 0; j < 8; ++j) acc[j] = 0.f;
#pragma unroll
    for (int k = 0; k < KK; ++k) {
        int id = __ldg(&nidx[n * KK + k]);
        float w = __ldg(&nw[n * KK + k]);
        const float* base = nrec + (size_t)id * RC;
        float e[8];
        float s = 0.f;
#pragma unroll
        for (int j = 0; j < 8; ++j) {
            float v = __expf(base[lane + 32 * j]);
            e[j] = v; s += v;
        }
#pragma unroll
        for (int o = 16; o; o >>= 1) s += __shfl_xor_sync(0xffffffffu, s, o);
        float ws = w / s;
#pragma unroll
        for (int j = 0; j < 8; ++j) acc[j] = fmaf(e[j], ws, acc[j]);
    }
    float e2[8];
    float s2 = 0.f;
#pragma unroll
    for (int j = 0; j < 8; ++j) { float v = __expf(acc[j]); e2[j] = v; s2 += v; }
#pragma unroll
    for (int o = 16; o; o >>= 1) s2 += __shfl_xor_sync(0xffffffffu, s2, o);
    float inv2 = 1.0f / s2;
    float tsum = 0.f;
#pragma unroll
    for (int j = 0; j < 8; ++j) tsum += e2[j];
    tsum *= inv2;
    float cs = tsum + __shfl_xor_sync(0xffffffffu, tsum, 16);
    float rs[8];
#pragma unroll
    for (int j = 0; j < 8; ++j) {
        float v = e2[j] * inv2;
        v += __shfl_xor_sync(0xffffffffu, v, 1);
        v += __shfl_xor_sync(0xffffffffu, v, 2);
        v += __shfl_xor_sync(0xffffffffu, v, 4);
        v += __shfl_xor_sync(0xffffffffu, v, 8);
        rs[j] = v;
    }
    float u = 0.f;
#pragma unroll
    for (int r = 0; r < 16; ++r) {
        float rw = __shfl_sync(0xffffffffu, rs[r >> 1], (r & 1) << 4);
        if (lane < 16) u = fmaf(rw, g_Ms[r * 16 + lane], u);
    }
    if (lane < 16) {
        g_U[(size_t)n * 16 + lane] = u;
        g_V[(size_t)n * 16 + lane] = cs;
    }
}

// ---------------- stage 3: P = exp2(U·V) tf32-rounded, Lr; zero pad tile ----------------
__global__ void k_smax() {
    int b = blockIdx.y;
    int qt = (gridDim.x - 1) - blockIdx.x;
    int tid = threadIdx.x;
    int row = tid >> 2, sub = tid & 3;
    int wid = tid >> 5, lane = tid & 31;
    int qg = qt * 64 + row;
    __shared__ float Vs[64 * 20];
    __shared__ float Ps[64 * 66];
    __shared__ float lsum[64];
    if (tid < 64) lsum[tid] = 0.f;
    float ur[16];
    const float* up = g_U + ((size_t)b * SS + qg) * 16;
#pragma unroll
    for (int i = 0; i < 16; ++i) ur[i] = up[i];

    for (int kt = 0; kt <= qt; ++kt) {
        __syncthreads();
        {
            int vr = tid >> 2, c4 = (tid & 3) * 4;
            float4 v = *(const float4*)(g_V + ((size_t)b * SS + (size_t)kt * 64 + vr) * 16 + c4);
            float* d = Vs + vr * 20 + c4;
            d[0] = v.x; d[1] = v.y; d[2] = v.z; d[3] = v.w;
        }
        __syncthreads();
        float psum = 0.f;
        bool diag = (kt == qt);
#pragma unroll
        for (int j = 0; j < 16; ++j) {
            int key = sub + 4 * j;
            const float* vv = Vs + key * 20;
            float s = 0.f;
#pragma unroll
            for (int i = 0; i < 16; ++i) s = fmaf(ur[i], vv[i], s);
            float p = (diag && key > row) ? 0.f : fexp2(s);
            Ps[row * 66 + key] = p;
            psum += p;
        }
        psum += __shfl_xor_sync(0xffffffffu, psum, 1);
        psum += __shfl_xor_sync(0xffffffffu, psum, 2);
        if (sub == 0) lsum[row] += psum;
        __syncthreads();
        float* gp = g_P + ((size_t)b * SS + (size_t)qt * 64) * SS + (size_t)kt * 64;
#pragma unroll
        for (int r = 0; r < 8; ++r) {
            int rr = wid * 8 + r;
            float2 v2 = *(float2*)(Ps + rr * 66 + 2 * lane);
            v2.x = tf32r(v2.x); v2.y = tf32r(v2.y);
            *(float2*)(gp + (size_t)rr * SS + 2 * lane) = v2;
        }
    }
    // zero the 64x64 tile above the diagonal (GEMM K tiles are 128-row aligned)
    if ((qt & 1) == 0) {
        float* gp = g_P + ((size_t)b * SS + (size_t)qt * 64) * SS + (size_t)(qt + 1) * 64;
#pragma unroll
        for (int r = 0; r < 8; ++r) {
            int rr = wid * 8 + r;
            *(float2*)(gp + (size_t)rr * SS + 2 * lane) = make_float2(0.f, 0.f);
        }
    }
    __syncthreads();
    if (tid < 64) g_Lr[(size_t)b * SS + (size_t)qt * 64 + tid] = 1.0f / lsum[tid];
}

// ---------------- stage 3b: x transpose (tf32) & W rounding ----------------
__global__ void k_xt(const float* __restrict__ x) {
    __shared__ float t[32][33];
    int b = blockIdx.z;
    int t0 = blockIdx.x * 32, d0 = blockIdx.y * 32;
    const float* xb = x + (size_t)b * SS * DD;
#pragma unroll
    for (int i = 0; i < 32; i += 8)
        t[threadIdx.y + i][threadIdx.x] = xb[(size_t)(t0 + threadIdx.y + i) * DD + d0 + threadIdx.x];
    __syncthreads();
    float* obp = g_Xt + (size_t)b * DD * SS;
#pragma unroll
    for (int i = 0; i < 32; i += 8)
        obp[(size_t)(d0 + threadIdx.y + i) * SS + t0 + threadIdx.x] = tf32r(t[threadIdx.x][threadIdx.y + i]);
}
__global__ void k_wr(const float* __restrict__ w) {
    int i = blockIdx.x * blockDim.x + threadIdx.x;
    g_Wr[i] = tf32r(w[i]);
}

// ---------------- mma.sync GEMM core: CTA tile M=128,N=128, K-chunks of 32 ----------------
__device__ __forceinline__ void load_chunk(float* sm, int buf,
                                           const float* Ag, int ldA,
                                           const float* Bg, int ldB,
                                           int k0, int tid) {
    uint32_t au = s2u(sm + buf * BUFSZ);
    uint32_t bu = au + ABUF * 4;
#pragma unroll
    for (int i = 0; i < 4; ++i) {
        int idx = tid + i * 256;
        int row = idx >> 3, c4 = idx & 7;
        cpa16(au + (row * APAD + c4 * 4) * 4, Ag + (size_t)row * ldA + k0 + c4 * 4);
    }
#pragma unroll
    for (int i = 0; i < 4; ++i) {
        int idx = tid + i * 256;
        int row = idx >> 3, c4 = idx & 7;
        cpa16(bu + (row * APAD + c4 * 4) * 4, Bg + (size_t)row * ldB + k0 + c4 * 4);
    }
    CPA_COMMIT();
}

__device__ __forceinline__ void gemm_mma(float* sm,
                                         const float* Ag, int ldA,
                                         const float* Bg, int ldB,
                                         int nch, float acc[4][4][4], int tid) {
    int wid = tid >> 5, lane = tid & 31;
    int g = lane >> 2, t = lane & 3;
    int wm = wid & 1, wn = wid >> 1;

    load_chunk(sm, 0, Ag, ldA, Bg, ldB, 0, tid);
    for (int c = 0; c < nch; ++c) {
        if (c + 1 < nch) {
            load_chunk(sm, (c + 1) & 1, Ag, ldA, Bg, ldB, (c + 1) * 32, tid);
            asm volatile("cp.async.wait_group 1;" ::: "memory");
        } else {
            asm volatile("cp.async.wait_group 0;" ::: "memory");
        }
        __syncthreads();
        const float* As = sm + (c & 1) * BUFSZ;
        const float* Bs = As + ABUF;
        const float* Ab = As + (wm * 64 + g) * APAD + t;
        const float* Bb = Bs + (wn * 32 + g) * APAD + t;
#pragma unroll
        for (int ks = 0; ks < 4; ++ks) {
            int k0 = ks * 8;
            uint32_t a[4][4], b[4][2];
#pragma unroll
            for (int m2 = 0; m2 < 4; ++m2) {
                const float* ap = Ab + m2 * 16 * APAD + k0;
                a[m2][0] = __float_as_uint(ap[0]);
                a[m2][1] = __float_as_uint(ap[8 * APAD]);
                a[m2][2] = __float_as_uint(ap[4]);
                a[m2][3] = __float_as_uint(ap[8 * APAD + 4]);
            }
#pragma unroll
            for (int n2 = 0; n2 < 4; ++n2) {
                const float* bp = Bb + n2 * 8 * APAD + k0;
                b[n2][0] = __float_as_uint(bp[0]);
                b[n2][1] = __float_as_uint(bp[4]);
            }
#pragma unroll
            for (int m2 = 0; m2 < 4; ++m2)
#pragma unroll
                for (int n2 = 0; n2 < 4; ++n2)
                    mma_tf32(acc[m2][n2], a[m2], b[n2]);
        }
        __syncthreads();
    }
}

// ---------------- stage 4: context GEMM + fused epilogue -> H ----------------
__global__ void __launch_bounds__(256, 2) k_ctx_mma(const float* __restrict__ alphap) {
    extern __shared__ __align__(16) float sm[];
    int mt = (gridDim.x - 1) - blockIdx.x;  // big tiles first
    int nt = blockIdx.y;
    int b = blockIdx.z;
    int tid = threadIdx.x;
    int wid = tid >> 5, lane = tid & 31;
    int g = lane >> 2, t = lane & 3;
    int wm = wid & 1, wn = wid >> 1;

    const float* Ag = g_P + ((size_t)b * SS + (size_t)mt * 128) * SS;
    const float* Bg = g_Xt + ((size_t)b * DD + (size_t)nt * 128) * SS;
    int nch = (mt + 1) * 4;

    float acc[4][4][4];
#pragma unroll
    for (int i = 0; i < 4; ++i)
#pragma unroll
        for (int j = 0; j < 4; ++j)
#pragma unroll
            for (int k = 0; k < 4; ++k) acc[i][j][k] = 0.f;

    gemm_mma(sm, Ag, SS, Bg, SS, nch, acc, tid);

    // epilogue staging (smem buffers are free now)
    float* Vq = sm;           // [128][16]
    float* lrs = sm + 2048;   // [128]
    float* c2 = sm + 2176;    // [16][128]
    for (int i = tid; i < 2048; i += 256)
        Vq[i] = g_V[((size_t)b * SS + (size_t)mt * 128) * 16 + i];
    if (tid < 128) lrs[tid] = g_Lr[(size_t)b * SS + mt * 128 + tid];
    for (int i = tid; i < 2048; i += 256) {
        int cc = i >> 7, d = i & 127;
        c2[i] = g_CB2[cc * DD + nt * 128 + d];
    }
    __syncthreads();

    float alpha = __ldg(alphap);
#pragma unroll
    for (int m2 = 0; m2 < 4; ++m2) {
#pragma unroll
        for (int rr = 0; rr < 2; ++rr) {
            int row = wm * 64 + m2 * 16 + g + rr * 8;
            float lr = lrs[row];
            const float* vr = Vq + row * 16;
            float* hrow = g_H + ((size_t)b * SS + (size_t)mt * 128 + row) * DD + nt * 128;
#pragma unroll
            for (int n2 = 0; n2 < 4; ++n2) {
                int col = wn * 32 + n2 * 8 + 2 * t;
                float tr0 = 0.f, tr1 = 0.f;
#pragma unroll
                for (int cc = 0; cc < 16; ++cc) {
                    float vv = vr[cc];
                    tr0 = fmaf(vv, c2[cc * 128 + col], tr0);
                    tr1 = fmaf(vv, c2[cc * 128 + col + 1], tr1);
                }
                float z0 = fmaf(acc[m2][n2][rr * 2 + 0], lr, alpha * tr0);
                float z1 = fmaf(acc[m2][n2][rr * 2 + 1], lr, alpha * tr1);
                z0 = tf32r(gelu_exact(z0));
                z1 = tf32r(gelu_exact(z1));
                *(float2*)(hrow + col) = make_float2(z0, z1);
            }
        }
    }
}

// ---------------- stage 5: out = H @ W^T + b ----------------
__global__ void __launch_bounds__(256, 2) k_out_mma(const float* __restrict__ ob,
                                                    float* __restrict__ out) {
    extern __shared__ __align__(16) float sm[];
    int mt = blockIdx.x;
    int nt = blockIdx.y;
    int tid = threadIdx.x;
    int wid = tid >> 5, lane = tid & 31;
    int g = lane >> 2, t = lane & 3;
    int wm = wid & 1, wn = wid >> 1;

    const float* Ag = g_H + (size_t)mt * 128 * DD;
    const float* Bg = g_Wr + (size_t)nt * 128 * DD;

    float acc[4][4][4];
#pragma unroll
    for (int i = 0; i < 4; ++i)
#pragma unroll
        for (int j = 0; j < 4; ++j)
#pragma unroll
            for (int k = 0; k < 4; ++k) acc[i][j][k] = 0.f;

    gemm_mma(sm, Ag, DD, Bg, DD, 32, acc, tid);

    float* bs = sm;
    if (tid < 128) bs[tid] = ob[nt * 128 + tid];
    __syncthreads();

#pragma unroll
    for (int m2 = 0; m2 < 4; ++m2) {
#pragma unroll
        for (int rr = 0; rr < 2; ++rr) {
            int row = wm * 64 + m2 * 16 + g + rr * 8;
            float* orow = out + ((size_t)mt * 128 + row) * DD + nt * 128;
#pragma unroll
            for (int n2 = 0; n2 < 4; ++n2) {
                int col = wn * 32 + n2 * 8 + 2 * t;
                float z0 = acc[m2][n2][rr * 2 + 0] + bs[col];
                float z1 = acc[m2][n2][rr * 2 + 1] + bs[col + 1];
                *(float2*)(orow + col) = make_float2(z0, z1);
            }
        }
    }
}

// ---------------- launcher ----------------
extern "C" void kernel_launch(void* const* d_in, const int* in_sizes, int n_in,
                              void* d_out, int out_size) {
    const float* x    = (const float*)d_in[0];
    const int*   nidx = (const int*)d_in[1];
    const float* nw   = (const float*)d_in[2];
    const float* nrec = (const float*)d_in[3];
    const float* rb   = (const float*)d_in[4];
    const float* cb   = (const float*)d_in[5];
    const float* ow   = (const float*)d_in[6];
    const float* ob   = (const float*)d_in[7];
    const float* alp  = (const float*)d_in[8];
    float* out = (float*)d_out;

    cudaFuncSetAttribute(k_ctx_mma, cudaFuncAttributeMaxDynamicSharedMemorySize, GSMEM_MMA);
    cudaFuncSetAttribute(k_out_mma, cudaFuncAttributeMaxDynamicSharedMemorySize, GSMEM_MMA);

    k_rbs<<<16, 256>>>(rb);
    k_cbs<<<512, 256>>>(cb);
    k_cb2<<<64, 256>>>(cb);
    k_M<<<1, 256>>>();
    k_route<<<(BB * SS * 32) / 256, 256>>>(nidx, nw, nrec);
    k_smax<<<dim3(64, BB), 256>>>();
    k_xt<<<dim3(SS / 32, DD / 32, BB), dim3(32, 8)>>>(x);
    k_wr<<<DD * DD / 256, 256>>>(ow);
    k_ctx_mma<<<dim3(32, 8, BB), 256, GSMEM_MMA>>>(alp);
    k_out_mma<<<dim3(BB * SS / 128, 8), 256, GSMEM_MMA>>>(ob, out);
}